// round 10
// baseline (speedup 1.0000x reference)
#include <cuda_runtime.h>

#define NTOT  65536
#define BGRAPH 64
#define NPG   1024
#define KC    128
#define DD    128
#define EDGES 1048576

// ---------------- scratch (device globals: allocation-free) ----------------
// g_deg starts zero (module load) and is RESTORED to zero by k_fill's
// countdown allocator every launch sequence -> no init kernel needed.
__device__ __align__(16) int g_deg[NTOT];
__device__ __align__(16) int g_off[NTOT + 4];
__device__ int g_adj[EDGES];

// ---------------- packed f32x2 helpers (Blackwell FFMA2 path) --------------
__device__ __forceinline__ unsigned long long pack2(float lo, float hi) {
    unsigned long long r;
    asm("mov.b64 %0, {%1, %2};" : "=l"(r) : "f"(lo), "f"(hi));
    return r;
}
__device__ __forceinline__ void ffma2(unsigned long long& d,
                                      unsigned long long a,
                                      unsigned long long b) {
    asm("fma.rn.f32x2 %0, %1, %2, %0;" : "+l"(d) : "l"(a), "l"(b));
}
__device__ __forceinline__ float2 unpack2(unsigned long long v) {
    float2 f;
    asm("mov.b64 {%0, %1}, %2;" : "=f"(f.x), "=f"(f.y) : "l"(v));
    return f;
}

// ---------------- edge dtype detect (per block, smem broadcast) ------------
__device__ __forceinline__ int detect_is64(const int* __restrict__ buf) {
    int az = 1;
#pragma unroll
    for (int k = 1; k <= 15; k += 2) az &= (buf[k] == 0);
    return az;
}
__device__ __forceinline__ int edge_id(const void* buf, int e, int is64) {
    return is64 ? (int)((const long long*)buf)[e] : ((const int*)buf)[e];
}

// ---------------- 1) degree count ----------------
__global__ void k_count(const void* __restrict__ dst) {
    __shared__ int s_is64;
    if (threadIdx.x == 0) s_is64 = detect_is64((const int*)dst);
    __syncthreads();
    int e = blockIdx.x * blockDim.x + threadIdx.x;
    if (e < EDGES) {
        int d = edge_id(dst, e, s_is64);
        if (d >= 0 && d < NTOT) atomicAdd(&g_deg[d], 1);
    }
}

// ---------------- 2) coalesced single-block exclusive scan -----------------
__global__ void k_scan() {
    __shared__ int warp_tot[32];
    __shared__ int warp_pre[32];
    int t = threadIdx.x;
    int lane = t & 31, w = t >> 5;
    const int4* deg4 = (const int4*)g_deg;
    int base4 = w * 512;

    int s = 0;
#pragma unroll
    for (int q = 0; q < 16; q++) {
        int4 v = deg4[base4 + q * 32 + lane];
        s += (v.x + v.y) + (v.z + v.w);
    }
#pragma unroll
    for (int o = 16; o > 0; o >>= 1) s += __shfl_xor_sync(0xffffffffu, s, o);
    if (lane == 0) warp_tot[w] = s;
    __syncthreads();

    if (w == 0) {
        int v = warp_tot[lane];
        int inc = v;
#pragma unroll
        for (int o = 1; o < 32; o <<= 1) {
            int u = __shfl_up_sync(0xffffffffu, inc, o);
            if (lane >= o) inc += u;
        }
        warp_pre[lane] = inc - v;
        if (lane == 31) g_off[NTOT] = inc;
    }
    __syncthreads();

    int run = warp_pre[w];
#pragma unroll
    for (int q = 0; q < 16; q++) {
        int4 v = deg4[base4 + q * 32 + lane];
        int ls = (v.x + v.y) + (v.z + v.w);
        int inc = ls;
#pragma unroll
        for (int o = 1; o < 32; o <<= 1) {
            int u = __shfl_up_sync(0xffffffffu, inc, o);
            if (lane >= o) inc += u;
        }
        int ex = run + inc - ls;
        int4 o4;
        o4.x = ex;
        o4.y = ex + v.x;
        o4.z = ex + v.x + v.y;
        o4.w = ex + v.x + v.y + v.z;
        ((int4*)g_off)[base4 + q * 32 + lane] = o4;
        run += __shfl_sync(0xffffffffu, inc, 31);
    }
}

// ---------------- 3) bucket fill (countdown: restores g_deg to 0) ----------
__global__ void k_fill(const void* __restrict__ src, const void* __restrict__ dst) {
    __shared__ int s_is64;
    if (threadIdx.x == 0) s_is64 = detect_is64((const int*)dst);
    __syncthreads();
    int e = blockIdx.x * blockDim.x + threadIdx.x;
    if (e < EDGES) {
        int d = edge_id(dst, e, s_is64);
        int s = edge_id(src, e, s_is64);
        if (d >= 0 && d < NTOT && s >= 0 && s < NTOT) {
            int pos = atomicAdd(&g_deg[d], -1) - 1;
            g_adj[g_off[d] + pos] = s;
        }
    }
}

// ------- 4) fused: neigh-gather + GEMM1 + bias/relu/softmax + GEMM2 --------
// Tile: 64 nodes x 128 cols, 256 threads (8 warps x 8 nodes).
// GEMM inner loops are software-pipelined: frags for kk+4 load while kk
// computes (hides the 29-cyc LDS latency that capped fma at 29%).
#define SMEM_FLOATS (64 * 256 + 256 * 128 + 128)
#define SMEM_BYTES  (SMEM_FLOATS * 4)

extern __shared__ float smem[];

// fragment loaders: W = 4 k-rows x 4 cols (per-lane), A = 8 nodes x 4 ks
__device__ __forceinline__ void loadW(float4 w_[4], const float* sWb,
                                      int kk, int c0, int ldw) {
#pragma unroll
    for (int q = 0; q < 4; q++)
        w_[q] = *(const float4*)(sWb + (kk + q) * ldw + c0);
}
__device__ __forceinline__ void loadA(float4 a_[8], const float* sAb,
                                      int kk, int n0, int lda) {
#pragma unroll
    for (int i = 0; i < 8; i++)
        a_[i] = *(const float4*)(sAb + (n0 + i) * lda + kk);
}
__device__ __forceinline__ float fcomp(const float4& v, int q) {
    return q == 0 ? v.x : (q == 1 ? v.y : (q == 2 ? v.z : v.w));
}
__device__ __forceinline__ void fma_step(unsigned long long acc[8][2],
                                         const float4 a_[8], const float4 w_[4]) {
#pragma unroll
    for (int q = 0; q < 4; q++) {
        unsigned long long w01 = pack2(fcomp(w_[q], 0), fcomp(w_[q], 1));
        unsigned long long w23 = pack2(fcomp(w_[q], 2), fcomp(w_[q], 3));
#pragma unroll
        for (int i = 0; i < 8; i++) {
            float av = fcomp(a_[i], q);
            unsigned long long aa = pack2(av, av);
            ffma2(acc[i][0], aa, w01);
            ffma2(acc[i][1], aa, w23);
        }
    }
}

__global__ void __launch_bounds__(256)
k_fused(const float* __restrict__ h,
        const float* __restrict__ fea,
        const float* __restrict__ Ws,
        const float* __restrict__ Wn,
        const float* __restrict__ bias,
        float* __restrict__ out) {
    float* sA = smem;                    // 64*256
    float* sW = smem + 64 * 256;         // 256*128
    float* sB = sW + 256 * 128;          // 128

    const int tid = threadIdx.x;
    const int node0 = blockIdx.x * 64;
    const int lane = tid & 31, wrp = tid >> 5;
    const int n0 = wrp * 8;
    const int c0 = lane * 4;

    // ---- bulk copies FIRST (their LDGs overlap the gather's latency) ----
    for (int i = tid; i < 64 * 32; i += 256) {
        int r = i >> 5, c = (i & 31) << 2;
        *(float4*)(sA + r * 256 + c) =
            *(const float4*)(h + (size_t)(node0 + r) * 128 + c);
    }
    for (int i = tid; i < 128 * 32; i += 256) {
        int r = i >> 5, c = (i & 31) << 2;
        *(float4*)(sW + r * 128 + c)         = *(const float4*)(Ws + r * 128 + c);
        *(float4*)(sW + (128 + r) * 128 + c) = *(const float4*)(Wn + r * 128 + c);
    }
    if (tid < 128) sB[tid] = bias[tid];

    // ---- neighbor aggregation: this warp's 8 nodes -> sA[..][128..255] ----
#pragma unroll 1
    for (int i = 0; i < 8; i++) {
        int node = node0 + n0 + i;
        int s = g_off[node], e = g_off[node + 1];
        float4 acc = make_float4(0.f, 0.f, 0.f, 0.f);
        int j = s;
        for (; j + 8 <= e; j += 8) {
            int idx[8];
#pragma unroll
            for (int q = 0; q < 8; q++) idx[q] = g_adj[j + q];
            float4 v[8];
#pragma unroll
            for (int q = 0; q < 8; q++)
                v[q] = __ldg((const float4*)(h + (size_t)idx[q] * 128) + lane);
#pragma unroll
            for (int q = 0; q < 8; q++) {
                acc.x += v[q].x; acc.y += v[q].y;
                acc.z += v[q].z; acc.w += v[q].w;
            }
        }
        for (; j < e; j++) {
            float4 v0 = __ldg((const float4*)(h + (size_t)g_adj[j] * 128) + lane);
            acc.x += v0.x; acc.y += v0.y; acc.z += v0.z; acc.w += v0.w;
        }
        float inv = 1.0f / fmaxf((float)(e - s), 1.0f);
        *(float4*)(sA + (n0 + i) * 256 + 128 + c0) =
            make_float4(acc.x * inv, acc.y * inv, acc.z * inv, acc.w * inv);
    }
    __syncthreads();

    // ---- GEMM1: logits = [h|neigh] @ [Ws;Wn]  (K=256), pipelined ----
    unsigned long long acc2[8][2];
#pragma unroll
    for (int i = 0; i < 8; i++) { acc2[i][0] = 0ULL; acc2[i][1] = 0ULL; }

    {
        float4 w0[4], a0[8], w1[4], a1[8];
        loadW(w0, sW, 0, c0, 128);
        loadA(a0, sA, 0, n0, 256);
#pragma unroll 1
        for (int kk = 0; kk < 256; kk += 8) {
            loadW(w1, sW, kk + 4, c0, 128);
            loadA(a1, sA, kk + 4, n0, 256);
            fma_step(acc2, a0, w0);
            int nk = (kk + 8 < 256) ? kk + 8 : 0;   // harmless reload at tail
            loadW(w0, sW, nk, c0, 128);
            loadA(a0, sA, nk, n0, 256);
            fma_step(acc2, a1, w1);
        }
    }

    // ---- bias + relu + row softmax (row in one warp: 4 cols/lane) ----
    float4 b4 = *(const float4*)(sB + c0);
    float probs[8][4];
#pragma unroll
    for (int i = 0; i < 8; i++) {
        float2 v01 = unpack2(acc2[i][0]);
        float2 v23 = unpack2(acc2[i][1]);
        float x0 = fmaxf(v01.x + b4.x, 0.f);
        float x1 = fmaxf(v01.y + b4.y, 0.f);
        float x2 = fmaxf(v23.x + b4.z, 0.f);
        float x3 = fmaxf(v23.y + b4.w, 0.f);
        float m = fmaxf(fmaxf(x0, x1), fmaxf(x2, x3));
#pragma unroll
        for (int o = 16; o > 0; o >>= 1)
            m = fmaxf(m, __shfl_xor_sync(0xffffffffu, m, o));
        x0 = __expf(x0 - m); x1 = __expf(x1 - m);
        x2 = __expf(x2 - m); x3 = __expf(x3 - m);
        float ssum = (x0 + x1) + (x2 + x3);
#pragma unroll
        for (int o = 16; o > 0; o >>= 1)
            ssum += __shfl_xor_sync(0xffffffffu, ssum, o);
        float inv = 1.0f / ssum;
        probs[i][0] = x0 * inv; probs[i][1] = x1 * inv;
        probs[i][2] = x2 * inv; probs[i][3] = x3 * inv;
    }

    __syncthreads();   // done reading sA/sW before aliasing

    float* sAssign = sA;   // [64][128]
    float* sFea    = sW;   // [128][128]
#pragma unroll
    for (int i = 0; i < 8; i++) {
        *(float4*)(sAssign + (n0 + i) * 128 + c0) =
            make_float4(probs[i][0], probs[i][1], probs[i][2], probs[i][3]);
    }
    {   // per-graph fea slice (graph = node0 / 1024)
        const float* feaG = fea + (size_t)(node0 >> 10) * KC * DD;
        for (int i = tid; i < 128 * 32; i += 256) {
            int r = i >> 5, c = (i & 31) << 2;
            *(float4*)(sFea + r * 128 + c) = *(const float4*)(feaG + r * 128 + c);
        }
    }
    __syncthreads();

    // ---- GEMM2: out = assign @ fea_g  (K=128), pipelined ----
    unsigned long long o2[8][2];
#pragma unroll
    for (int i = 0; i < 8; i++) { o2[i][0] = 0ULL; o2[i][1] = 0ULL; }

    {
        float4 w0[4], a0[8], w1[4], a1[8];
        loadW(w0, sFea, 0, c0, 128);
        loadA(a0, sAssign, 0, n0, 128);
#pragma unroll 1
        for (int kk = 0; kk < 128; kk += 8) {
            loadW(w1, sFea, kk + 4, c0, 128);
            loadA(a1, sAssign, kk + 4, n0, 128);
            fma_step(o2, a0, w0);
            int nk = (kk + 8 < 128) ? kk + 8 : 0;
            loadW(w0, sFea, nk, c0, 128);
            loadA(a0, sAssign, nk, n0, 128);
            fma_step(o2, a1, w1);
        }
    }

#pragma unroll
    for (int i = 0; i < 8; i++) {
        float2 v01 = unpack2(o2[i][0]);
        float2 v23 = unpack2(o2[i][1]);
        *(float4*)(out + (size_t)(node0 + n0 + i) * 128 + c0) =
            make_float4(v01.x, v01.y, v23.x, v23.y);
    }
}

// ---------------- launch (4 kernels; profiler lands on k_fused = #4) -------
extern "C" void kernel_launch(void* const* d_in, const int* in_sizes, int n_in,
                              void* d_out, int out_size) {
    (void)in_sizes; (void)n_in; (void)out_size;
    const float* h    = (const float*)d_in[0];
    const float* fea  = (const float*)d_in[1];
    const float* Ws   = (const float*)d_in[2];
    const float* Wn   = (const float*)d_in[3];
    const float* bias = (const float*)d_in[4];
    const void*  esrc = d_in[5];
    const void*  edst = d_in[6];
    float* out = (float*)d_out;

    cudaFuncSetAttribute(k_fused, cudaFuncAttributeMaxDynamicSharedMemorySize,
                         SMEM_BYTES);

    k_count<<<(EDGES + 255) / 256, 256>>>(edst);
    k_scan <<<1, 1024>>>();
    k_fill <<<(EDGES + 255) / 256, 256>>>(esrc, edst);
    k_fused<<<NTOT / 64, 256, SMEM_BYTES>>>(h, fea, Ws, Wn, bias, out);
}

// round 11
// speedup vs baseline: 1.1941x; 1.1941x over previous
#include <cuda_runtime.h>

#define NTOT  65536
#define BGRAPH 64
#define NPG   1024
#define KC    128
#define DD    128
#define EDGES 1048576

// ---------------- scratch (device globals: allocation-free) ----------------
__device__ __align__(16) int g_deg[NTOT];
__device__ __align__(16) int g_off[NTOT + 4];
__device__ int g_adj[EDGES];

typedef unsigned long long ull;

// packed f32x2 fma: d.{lo,hi} += a.{lo,hi} * b.{lo,hi}
__device__ __forceinline__ void ffma2(ull& d, ull a, ull b) {
    asm("fma.rn.f32x2 %0, %1, %2, %0;" : "+l"(d) : "l"(a), "l"(b));
}
__device__ __forceinline__ float2 unpack2(ull v) {
    float2 f;
    asm("mov.b64 {%0, %1}, %2;" : "=f"(f.x), "=f"(f.y) : "l"(v));
    return f;
}

// ---------------- edge dtype detect ----------------
__device__ __forceinline__ int detect_is64(const int* __restrict__ buf) {
    int az = 1;
#pragma unroll
    for (int k = 1; k <= 15; k += 2) az &= (buf[k] == 0);
    return az;
}
__device__ __forceinline__ int edge_id(const void* buf, int e, int is64) {
    return is64 ? (int)((const long long*)buf)[e] : ((const int*)buf)[e];
}

// ---------------- 1) degree count ----------------
__global__ void k_count(const void* __restrict__ dst) {
    __shared__ int s_is64;
    if (threadIdx.x == 0) s_is64 = detect_is64((const int*)dst);
    __syncthreads();
    int e = blockIdx.x * blockDim.x + threadIdx.x;
    if (e < EDGES) {
        int d = edge_id(dst, e, s_is64);
        if (d >= 0 && d < NTOT) atomicAdd(&g_deg[d], 1);
    }
}

// ---------------- 2) coalesced single-block exclusive scan -----------------
__global__ void k_scan() {
    __shared__ int warp_tot[32];
    __shared__ int warp_pre[32];
    int t = threadIdx.x;
    int lane = t & 31, w = t >> 5;
    const int4* deg4 = (const int4*)g_deg;
    int base4 = w * 512;

    int s = 0;
#pragma unroll
    for (int q = 0; q < 16; q++) {
        int4 v = deg4[base4 + q * 32 + lane];
        s += (v.x + v.y) + (v.z + v.w);
    }
#pragma unroll
    for (int o = 16; o > 0; o >>= 1) s += __shfl_xor_sync(0xffffffffu, s, o);
    if (lane == 0) warp_tot[w] = s;
    __syncthreads();

    if (w == 0) {
        int v = warp_tot[lane];
        int inc = v;
#pragma unroll
        for (int o = 1; o < 32; o <<= 1) {
            int u = __shfl_up_sync(0xffffffffu, inc, o);
            if (lane >= o) inc += u;
        }
        warp_pre[lane] = inc - v;
        if (lane == 31) g_off[NTOT] = inc;
    }
    __syncthreads();

    int run = warp_pre[w];
#pragma unroll
    for (int q = 0; q < 16; q++) {
        int4 v = deg4[base4 + q * 32 + lane];
        int ls = (v.x + v.y) + (v.z + v.w);
        int inc = ls;
#pragma unroll
        for (int o = 1; o < 32; o <<= 1) {
            int u = __shfl_up_sync(0xffffffffu, inc, o);
            if (lane >= o) inc += u;
        }
        int ex = run + inc - ls;
        int4 o4;
        o4.x = ex;
        o4.y = ex + v.x;
        o4.z = ex + v.x + v.y;
        o4.w = ex + v.x + v.y + v.z;
        ((int4*)g_off)[base4 + q * 32 + lane] = o4;
        run += __shfl_sync(0xffffffffu, inc, 31);
    }
}

// ---------------- 3) bucket fill (countdown: restores g_deg to 0) ----------
__global__ void k_fill(const void* __restrict__ src, const void* __restrict__ dst) {
    __shared__ int s_is64;
    if (threadIdx.x == 0) s_is64 = detect_is64((const int*)dst);
    __syncthreads();
    int e = blockIdx.x * blockDim.x + threadIdx.x;
    if (e < EDGES) {
        int d = edge_id(dst, e, s_is64);
        int s = edge_id(src, e, s_is64);
        if (d >= 0 && d < NTOT && s >= 0 && s < NTOT) {
            int pos = atomicAdd(&g_deg[d], -1) - 1;
            g_adj[g_off[d] + pos] = s;
        }
    }
}

// ------- 4) fused: gather + GEMM1 + bias/relu/softmax + GEMM2 --------------
// 256 threads (8 warps x 8 nodes), 64-node tile, 2 CTAs/SM.
// Weights/fea stream through one 16k x 128c smem chunk, stored TRANSPOSED
// (sT[c][k], row stride 18) so k-pairs are contiguous 8B -> mov-free f32x2.
// Thread's 4 cols: c = lane + 32*j, j=0..3.
#define CH 16                      // k rows per chunk
#define TPAD 18                    // transposed row stride (even: 8B-aligned pairs)
#define SA_FLOATS (64 * 256)       // A tile [64][256]
#define ST_FLOATS (128 * TPAD)     // chunk buffer
#define SMEM_FLOATS (SA_FLOATS + ST_FLOATS + 128)
#define SMEM_BYTES  (SMEM_FLOATS * 4)

extern __shared__ float smem[];

__global__ void __launch_bounds__(256, 2)
k_fused(const float* __restrict__ h,
        const float* __restrict__ fea,
        const float* __restrict__ Ws,
        const float* __restrict__ Wn,
        const float* __restrict__ bias,
        float* __restrict__ out) {
    float* sA = smem;                       // [64][256]
    float* sT = smem + SA_FLOATS;           // [128][TPAD] transposed chunk
    float* sB = sT + ST_FLOATS;             // [128]

    const int tid = threadIdx.x;
    const int node0 = blockIdx.x * 64;
    const int lane = tid & 31, wrp = tid >> 5;
    const int n0 = wrp * 8;                 // this warp's 8 nodes
    // chunk-loader coords: rows r0=tid/32, r0+8; col c4=(tid&31)*4
    const int lr0 = tid >> 5;
    const int lc4 = (tid & 31) << 2;

    // ---- bulk copy h -> sA[..][0..127] (LDGs overlap gather latency) ----
    for (int i = tid; i < 64 * 32; i += 256) {
        int r = i >> 5, c = (i & 31) << 2;
        *(float4*)(sA + r * 256 + c) =
            *(const float4*)(h + (size_t)(node0 + r) * 128 + c);
    }
    if (tid < 128) sB[tid] = bias[tid];

    // ---- neighbor aggregation -> sA[..][128..255] ----
#pragma unroll 1
    for (int i = 0; i < 8; i++) {
        int node = node0 + n0 + i;
        int s = g_off[node], e = g_off[node + 1];
        float4 acc = make_float4(0.f, 0.f, 0.f, 0.f);
        int j = s;
        for (; j + 8 <= e; j += 8) {
            int idx[8];
#pragma unroll
            for (int q = 0; q < 8; q++) idx[q] = g_adj[j + q];
            float4 v[8];
#pragma unroll
            for (int q = 0; q < 8; q++)
                v[q] = __ldg((const float4*)(h + (size_t)idx[q] * 128) + lane);
#pragma unroll
            for (int q = 0; q < 8; q++) {
                acc.x += v[q].x; acc.y += v[q].y;
                acc.z += v[q].z; acc.w += v[q].w;
            }
        }
        for (; j < e; j++) {
            float4 v0 = __ldg((const float4*)(h + (size_t)g_adj[j] * 128) + lane);
            acc.x += v0.x; acc.y += v0.y; acc.z += v0.z; acc.w += v0.w;
        }
        float inv = 1.0f / fmaxf((float)(e - s), 1.0f);
        *(float4*)(sA + (n0 + i) * 256 + 128 + lane * 4) =
            make_float4(acc.x * inv, acc.y * inv, acc.z * inv, acc.w * inv);
    }

    // =============== GEMM1: logits = [h|neigh] @ [Ws;Wn], K=256 ===========
    ull acc1[8][4];
#pragma unroll
    for (int i = 0; i < 8; i++)
#pragma unroll
        for (int j = 0; j < 4; j++) acc1[i][j] = 0ULL;

    float4 f0, f1;   // in-flight chunk (2 rows x 4 cols per thread)
    {   // prologue: fetch chunk 0
        int k0 = lr0, k1 = lr0 + 8;
        f0 = *(const float4*)(Ws + (size_t)k0 * 128 + lc4);
        f1 = *(const float4*)(Ws + (size_t)k1 * 128 + lc4);
    }
    // store chunk 0 transposed
    sT[(lc4 + 0) * TPAD + lr0] = f0.x; sT[(lc4 + 1) * TPAD + lr0] = f0.y;
    sT[(lc4 + 2) * TPAD + lr0] = f0.z; sT[(lc4 + 3) * TPAD + lr0] = f0.w;
    sT[(lc4 + 0) * TPAD + lr0 + 8] = f1.x; sT[(lc4 + 1) * TPAD + lr0 + 8] = f1.y;
    sT[(lc4 + 2) * TPAD + lr0 + 8] = f1.z; sT[(lc4 + 3) * TPAD + lr0 + 8] = f1.w;
    __syncthreads();

#pragma unroll 1
    for (int ch = 0; ch < 16; ch++) {
        // prefetch next chunk to regs
        if (ch + 1 < 16) {
            int k0 = (ch + 1) * CH + lr0;
            int k1 = k0 + 8;
            const float* W0 = (k0 < 128) ? (Ws + (size_t)k0 * 128)
                                         : (Wn + (size_t)(k0 - 128) * 128);
            const float* W1 = (k1 < 128) ? (Ws + (size_t)k1 * 128)
                                         : (Wn + (size_t)(k1 - 128) * 128);
            f0 = *(const float4*)(W0 + lc4);
            f1 = *(const float4*)(W1 + lc4);
        }
        // compute this chunk: 8 k-pairs
        const int kbase = ch * CH;
#pragma unroll
        for (int kp = 0; kp < CH / 2; kp++) {
            ull w_[4], a_[8];
#pragma unroll
            for (int j = 0; j < 4; j++)
                w_[j] = *(const ull*)(sT + (lane + 32 * j) * TPAD + 2 * kp);
#pragma unroll
            for (int i = 0; i < 8; i++)
                a_[i] = *(const ull*)(sA + (n0 + i) * 256 + kbase + 2 * kp);
#pragma unroll
            for (int i = 0; i < 8; i++)
#pragma unroll
                for (int j = 0; j < 4; j++)
                    ffma2(acc1[i][j], a_[i], w_[j]);
        }
        __syncthreads();
        if (ch + 1 < 16) {
            sT[(lc4 + 0) * TPAD + lr0] = f0.x; sT[(lc4 + 1) * TPAD + lr0] = f0.y;
            sT[(lc4 + 2) * TPAD + lr0] = f0.z; sT[(lc4 + 3) * TPAD + lr0] = f0.w;
            sT[(lc4 + 0) * TPAD + lr0 + 8] = f1.x; sT[(lc4 + 1) * TPAD + lr0 + 8] = f1.y;
            sT[(lc4 + 2) * TPAD + lr0 + 8] = f1.z; sT[(lc4 + 3) * TPAD + lr0 + 8] = f1.w;
            __syncthreads();
        }
    }

    // ---- bias + relu + row softmax (cols c = lane+32j live in this warp) --
    float b_[4];
#pragma unroll
    for (int j = 0; j < 4; j++) b_[j] = sB[lane + 32 * j];

    float probs[8][4];
#pragma unroll
    for (int i = 0; i < 8; i++) {
        float x[4];
#pragma unroll
        for (int j = 0; j < 4; j++) {
            float2 p = unpack2(acc1[i][j]);
            x[j] = fmaxf(p.x + p.y + b_[j], 0.f);
        }
        float m = fmaxf(fmaxf(x[0], x[1]), fmaxf(x[2], x[3]));
#pragma unroll
        for (int o = 16; o > 0; o >>= 1)
            m = fmaxf(m, __shfl_xor_sync(0xffffffffu, m, o));
        float ssum = 0.f;
#pragma unroll
        for (int j = 0; j < 4; j++) { x[j] = __expf(x[j] - m); ssum += x[j]; }
#pragma unroll
        for (int o = 16; o > 0; o >>= 1)
            ssum += __shfl_xor_sync(0xffffffffu, ssum, o);
        float inv = 1.0f / ssum;
#pragma unroll
        for (int j = 0; j < 4; j++) probs[i][j] = x[j] * inv;
    }

    __syncthreads();   // all reads of sA (GEMM1 A-side) complete

    // assign -> sA region (rows of 128, k-contiguous for GEMM2 pairs)
    float* sAssign = sA;   // [64][128]
#pragma unroll
    for (int i = 0; i < 8; i++)
#pragma unroll
        for (int j = 0; j < 4; j++)
            sAssign[(n0 + i) * 128 + lane + 32 * j] = probs[i][j];

    // =============== GEMM2: out = assign @ fea_g, K=128 ====================
    ull acc2[8][4];
#pragma unroll
    for (int i = 0; i < 8; i++)
#pragma unroll
        for (int j = 0; j < 4; j++) acc2[i][j] = 0ULL;

    const float* feaG = fea + (size_t)(node0 >> 10) * KC * DD;
    {   // prologue: fetch fea chunk 0
        f0 = *(const float4*)(feaG + (size_t)lr0 * 128 + lc4);
        f1 = *(const float4*)(feaG + (size_t)(lr0 + 8) * 128 + lc4);
    }
    __syncthreads();   // assign writes + last W-chunk reads done
    sT[(lc4 + 0) * TPAD + lr0] = f0.x; sT[(lc4 + 1) * TPAD + lr0] = f0.y;
    sT[(lc4 + 2) * TPAD + lr0] = f0.z; sT[(lc4 + 3) * TPAD + lr0] = f0.w;
    sT[(lc4 + 0) * TPAD + lr0 + 8] = f1.x; sT[(lc4 + 1) * TPAD + lr0 + 8] = f1.y;
    sT[(lc4 + 2) * TPAD + lr0 + 8] = f1.z; sT[(lc4 + 3) * TPAD + lr0 + 8] = f1.w;
    __syncthreads();

#pragma unroll 1
    for (int ch = 0; ch < 8; ch++) {
        if (ch + 1 < 8) {
            int k0 = (ch + 1) * CH + lr0;
            f0 = *(const float4*)(feaG + (size_t)k0 * 128 + lc4);
            f1 = *(const float4*)(feaG + (size_t)(k0 + 8) * 128 + lc4);
        }
        const int kbase = ch * CH;
#pragma unroll
        for (int kp = 0; kp < CH / 2; kp++) {
            ull w_[4], a_[8];
#pragma unroll
            for (int j = 0; j < 4; j++)
                w_[j] = *(const ull*)(sT + (lane + 32 * j) * TPAD + 2 * kp);
#pragma unroll
            for (int i = 0; i < 8; i++)
                a_[i] = *(const ull*)(sAssign + (n0 + i) * 128 + kbase + 2 * kp);
#pragma unroll
            for (int i = 0; i < 8; i++)
#pragma unroll
                for (int j = 0; j < 4; j++)
                    ffma2(acc2[i][j], a_[i], w_[j]);
        }
        __syncthreads();
        if (ch + 1 < 8) {
            sT[(lc4 + 0) * TPAD + lr0] = f0.x; sT[(lc4 + 1) * TPAD + lr0] = f0.y;
            sT[(lc4 + 2) * TPAD + lr0] = f0.z; sT[(lc4 + 3) * TPAD + lr0] = f0.w;
            sT[(lc4 + 0) * TPAD + lr0 + 8] = f1.x; sT[(lc4 + 1) * TPAD + lr0 + 8] = f1.y;
            sT[(lc4 + 2) * TPAD + lr0 + 8] = f1.z; sT[(lc4 + 3) * TPAD + lr0 + 8] = f1.w;
            __syncthreads();
        }
    }

    // ---- write out: out[node][lane+32j] ----
#pragma unroll
    for (int i = 0; i < 8; i++) {
        float* orow = out + (size_t)(node0 + n0 + i) * 128;
#pragma unroll
        for (int j = 0; j < 4; j++) {
            float2 p = unpack2(acc2[i][j]);
            orow[lane + 32 * j] = p.x + p.y;
        }
    }
}

// ---------------- launch (4 kernels; profiler lands on k_fused = #4) -------
extern "C" void kernel_launch(void* const* d_in, const int* in_sizes, int n_in,
                              void* d_out, int out_size) {
    (void)in_sizes; (void)n_in; (void)out_size;
    const float* h    = (const float*)d_in[0];
    const float* fea  = (const float*)d_in[1];
    const float* Ws   = (const float*)d_in[2];
    const float* Wn   = (const float*)d_in[3];
    const float* bias = (const float*)d_in[4];
    const void*  esrc = d_in[5];
    const void*  edst = d_in[6];
    float* out = (float*)d_out;

    cudaFuncSetAttribute(k_fused, cudaFuncAttributeMaxDynamicSharedMemorySize,
                         SMEM_BYTES);

    k_count<<<(EDGES + 255) / 256, 256>>>(edst);
    k_scan <<<1, 1024>>>();
    k_fill <<<(EDGES + 255) / 256, 256>>>(esrc, edst);
    k_fused<<<NTOT / 64, 256, SMEM_BYTES>>>(h, fea, Ws, Wn, bias, out);
}

// round 13
// speedup vs baseline: 1.2878x; 1.0785x over previous
#include <cuda_runtime.h>

#define NTOT  65536
#define BGRAPH 64
#define NPG   1024
#define KC    128
#define DD    128
#define EDGES 1048576

// ---------------- scratch (device globals: allocation-free) ----------------
__device__ __align__(16) int g_deg[NTOT];
__device__ __align__(16) int g_off[NTOT + 4];
__device__ int g_adj[EDGES];

typedef unsigned long long ull;

__device__ __forceinline__ void ffma2(ull& d, ull a, ull b) {
    asm("fma.rn.f32x2 %0, %1, %2, %0;" : "+l"(d) : "l"(a), "l"(b));
}
__device__ __forceinline__ float2 unpack2(ull v) {
    float2 f;
    asm("mov.b64 {%0, %1}, %2;" : "=f"(f.x), "=f"(f.y) : "l"(v));
    return f;
}

// ---------------- edge dtype detect ----------------
__device__ __forceinline__ int detect_is64(const int* __restrict__ buf) {
    int az = 1;
#pragma unroll
    for (int k = 1; k <= 15; k += 2) az &= (buf[k] == 0);
    return az;
}
__device__ __forceinline__ int edge_id(const void* buf, int e, int is64) {
    return is64 ? (int)((const long long*)buf)[e] : ((const int*)buf)[e];
}

// ---------------- 1) degree count ----------------
__global__ void k_count(const void* __restrict__ dst) {
    __shared__ int s_is64;
    if (threadIdx.x == 0) s_is64 = detect_is64((const int*)dst);
    __syncthreads();
    int e = blockIdx.x * blockDim.x + threadIdx.x;
    if (e < EDGES) {
        int d = edge_id(dst, e, s_is64);
        if (d >= 0 && d < NTOT) atomicAdd(&g_deg[d], 1);
    }
}

// ---------------- 2) coalesced single-block exclusive scan -----------------
__global__ void k_scan() {
    __shared__ int warp_tot[32];
    __shared__ int warp_pre[32];
    int t = threadIdx.x;
    int lane = t & 31, w = t >> 5;
    const int4* deg4 = (const int4*)g_deg;
    int base4 = w * 512;

    int s = 0;
#pragma unroll
    for (int q = 0; q < 16; q++) {
        int4 v = deg4[base4 + q * 32 + lane];
        s += (v.x + v.y) + (v.z + v.w);
    }
#pragma unroll
    for (int o = 16; o > 0; o >>= 1) s += __shfl_xor_sync(0xffffffffu, s, o);
    if (lane == 0) warp_tot[w] = s;
    __syncthreads();

    if (w == 0) {
        int v = warp_tot[lane];
        int inc = v;
#pragma unroll
        for (int o = 1; o < 32; o <<= 1) {
            int u = __shfl_up_sync(0xffffffffu, inc, o);
            if (lane >= o) inc += u;
        }
        warp_pre[lane] = inc - v;
        if (lane == 31) g_off[NTOT] = inc;
    }
    __syncthreads();

    int run = warp_pre[w];
#pragma unroll
    for (int q = 0; q < 16; q++) {
        int4 v = deg4[base4 + q * 32 + lane];
        int ls = (v.x + v.y) + (v.z + v.w);
        int inc = ls;
#pragma unroll
        for (int o = 1; o < 32; o <<= 1) {
            int u = __shfl_up_sync(0xffffffffu, inc, o);
            if (lane >= o) inc += u;
        }
        int ex = run + inc - ls;
        int4 o4;
        o4.x = ex;
        o4.y = ex + v.x;
        o4.z = ex + v.x + v.y;
        o4.w = ex + v.x + v.y + v.z;
        ((int4*)g_off)[base4 + q * 32 + lane] = o4;
        run += __shfl_sync(0xffffffffu, inc, 31);
    }
}

// ---------------- 3) bucket fill (countdown: restores g_deg to 0) ----------
__global__ void k_fill(const void* __restrict__ src, const void* __restrict__ dst) {
    __shared__ int s_is64;
    if (threadIdx.x == 0) s_is64 = detect_is64((const int*)dst);
    __syncthreads();
    int e = blockIdx.x * blockDim.x + threadIdx.x;
    if (e < EDGES) {
        int d = edge_id(dst, e, s_is64);
        int s = edge_id(src, e, s_is64);
        if (d >= 0 && d < NTOT && s >= 0 && s < NTOT) {
            int pos = atomicAdd(&g_deg[d], -1) - 1;
            g_adj[g_off[d] + pos] = s;
        }
    }
}

// ------- 4) fused: gather + GEMM1 + bias/relu/softmax + GEMM2 --------------
// 256 threads (8 warps x 8 nodes), 64-node tile, 2 CTAs/SM.
// W/fea stream through DOUBLE-BUFFERED 16k x 128c transposed chunks
// (sT[c][k], stride 18): k-pairs contiguous 8B -> mov-free f32x2 LDS.64.
// Loader uses scalar LDG.32 (k=wrp+8m, c=lane+32j) so the transposed STS.32
// is only 2-way conflicted (was 8-way). ONE __syncthreads per chunk.
#define CH 16
#define TPAD 18
#define SA_FLOATS (64 * 256)
#define ST_FLOATS (128 * TPAD)
#define SMEM_FLOATS (SA_FLOATS + 2 * ST_FLOATS + 128)
#define SMEM_BYTES  (SMEM_FLOATS * 4)

extern __shared__ float smem[];

__global__ void __launch_bounds__(256, 2)
k_fused(const float* __restrict__ h,
        const float* __restrict__ fea,
        const float* __restrict__ Ws,
        const float* __restrict__ Wn,
        const float* __restrict__ bias,
        float* __restrict__ out) {
    float* sA  = smem;                       // [64][256]
    float* sT0 = smem + SA_FLOATS;           // chunk buf 0: [128][TPAD]
    float* sT1 = sT0 + ST_FLOATS;            // chunk buf 1
    float* sB  = sT1 + ST_FLOATS;            // [128]

    const int tid = threadIdx.x;
    const int node0 = blockIdx.x * 64;
    const int lane = tid & 31, wrp = tid >> 5;
    const int n0 = wrp * 8;

    // ---- bulk copy h -> sA[..][0..127] (LDGs overlap gather latency) ----
    for (int i = tid; i < 64 * 32; i += 256) {
        int r = i >> 5, c = (i & 31) << 2;
        *(float4*)(sA + r * 256 + c) =
            *(const float4*)(h + (size_t)(node0 + r) * 128 + c);
    }
    if (tid < 128) sB[tid] = bias[tid];

    // ---- neighbor aggregation -> sA[..][128..255] ----
#pragma unroll 1
    for (int i = 0; i < 8; i++) {
        int node = node0 + n0 + i;
        int s = g_off[node], e = g_off[node + 1];
        float4 acc = make_float4(0.f, 0.f, 0.f, 0.f);
        int j = s;
        for (; j + 8 <= e; j += 8) {
            int idx[8];
#pragma unroll
            for (int q = 0; q < 8; q++) idx[q] = g_adj[j + q];
            float4 v[8];
#pragma unroll
            for (int q = 0; q < 8; q++)
                v[q] = __ldg((const float4*)(h + (size_t)idx[q] * 128) + lane);
#pragma unroll
            for (int q = 0; q < 8; q++) {
                acc.x += v[q].x; acc.y += v[q].y;
                acc.z += v[q].z; acc.w += v[q].w;
            }
        }
        for (; j < e; j++) {
            float4 v0 = __ldg((const float4*)(h + (size_t)g_adj[j] * 128) + lane);
            acc.x += v0.x; acc.y += v0.y; acc.z += v0.z; acc.w += v0.w;
        }
        float inv = 1.0f / fmaxf((float)(e - s), 1.0f);
        *(float4*)(sA + (n0 + i) * 256 + 128 + lane * 4) =
            make_float4(acc.x * inv, acc.y * inv, acc.z * inv, acc.w * inv);
    }

    // chunk loader: p[m*4+j] = row(k = kb+wrp+8m)[lane+32j]  (coalesced LDG.32)
    auto ld_w = [&](int ch, float p[8]) {
        int kb = ch * CH;
#pragma unroll
        for (int m = 0; m < 2; m++) {
            int k = kb + wrp + 8 * m;
            const float* row = (k < 128) ? (Ws + (size_t)k * 128)
                                         : (Wn + (size_t)(k - 128) * 128);
#pragma unroll
            for (int j = 0; j < 4; j++) p[m * 4 + j] = __ldg(row + lane + 32 * j);
        }
    };
    auto ld_f = [&](const float* feaG, int ch, float p[8]) {
        int kb = ch * CH;
#pragma unroll
        for (int m = 0; m < 2; m++) {
            const float* row = feaG + (size_t)(kb + wrp + 8 * m) * 128;
#pragma unroll
            for (int j = 0; j < 4; j++) p[m * 4 + j] = __ldg(row + lane + 32 * j);
        }
    };
    // transposed store: STS.32 lane-stride TPAD floats -> 2-way only
    auto st_chunk = [&](float* buf, const float p[8]) {
#pragma unroll
        for (int m = 0; m < 2; m++)
#pragma unroll
            for (int j = 0; j < 4; j++)
                buf[(lane + 32 * j) * TPAD + wrp + 8 * m] = p[m * 4 + j];
    };
    // compute one 16-k chunk: mov-free f32x2 (A broadcast LDS.64, W LDS.64)
    auto compute = [&](const float* buf, const float* Arow0, int lda, ull acc[8][4]) {
#pragma unroll
        for (int kp = 0; kp < CH / 2; kp++) {
            ull w_[4];
#pragma unroll
            for (int j = 0; j < 4; j++)
                w_[j] = *(const ull*)(buf + (lane + 32 * j) * TPAD + 2 * kp);
            ull a_[8];
#pragma unroll
            for (int i = 0; i < 8; i++)
                a_[i] = *(const ull*)(Arow0 + i * lda + 2 * kp);
#pragma unroll
            for (int i = 0; i < 8; i++)
#pragma unroll
                for (int j = 0; j < 4; j++)
                    ffma2(acc[i][j], a_[i], w_[j]);
        }
    };

    // =============== GEMM1: logits = [h|neigh] @ [Ws;Wn], K=256 ============
    ull acc1[8][4];
#pragma unroll
    for (int i = 0; i < 8; i++)
#pragma unroll
        for (int j = 0; j < 4; j++) acc1[i][j] = 0ULL;

    float p[8];
    ld_w(0, p);
    st_chunk(sT0, p);
    __syncthreads();
    ld_w(1, p);

#pragma unroll 1
    for (int ch = 0; ch < 16; ch++) {
        float* cur = (ch & 1) ? sT1 : sT0;
        float* nxt = (ch & 1) ? sT0 : sT1;
        if (ch + 1 < 16) st_chunk(nxt, p);       // buf last read at ch-1 (synced)
        if (ch + 2 < 16) ld_w(ch + 2, p);        // LDG covered by this compute
        compute(cur, sA + n0 * 256 + ch * CH, 256, acc1);
        __syncthreads();
    }

    // ---- bias + relu + row softmax (cols c = lane+32j live in this warp) --
    float b_[4];
#pragma unroll
    for (int j = 0; j < 4; j++) b_[j] = sB[lane + 32 * j];

    float probs[8][4];
#pragma unroll
    for (int i = 0; i < 8; i++) {
        float x[4];
#pragma unroll
        for (int j = 0; j < 4; j++) {
            float2 q = unpack2(acc1[i][j]);
            x[j] = fmaxf(q.x + q.y + b_[j], 0.f);
        }
        float m = fmaxf(fmaxf(x[0], x[1]), fmaxf(x[2], x[3]));
#pragma unroll
        for (int o = 16; o > 0; o >>= 1)
            m = fmaxf(m, __shfl_xor_sync(0xffffffffu, m, o));
        float ssum = 0.f;
#pragma unroll
        for (int j = 0; j < 4; j++) { x[j] = __expf(x[j] - m); ssum += x[j]; }
#pragma unroll
        for (int o = 16; o > 0; o >>= 1)
            ssum += __shfl_xor_sync(0xffffffffu, ssum, o);
        float inv = 1.0f / ssum;
#pragma unroll
        for (int j = 0; j < 4; j++) probs[i][j] = x[j] * inv;
    }

    // assign rows (own warp's rows only -> no sync needed before own reads)
    float* sAssign = sA;   // [64][128]
#pragma unroll
    for (int i = 0; i < 8; i++)
#pragma unroll
        for (int j = 0; j < 4; j++)
            sAssign[(n0 + i) * 128 + lane + 32 * j] = probs[i][j];

    // =============== GEMM2: out = assign @ fea_g, K=128 ====================
    ull acc2[8][4];
#pragma unroll
    for (int i = 0; i < 8; i++)
#pragma unroll
        for (int j = 0; j < 4; j++) acc2[i][j] = 0ULL;

    const float* feaG = fea + (size_t)(node0 >> 10) * KC * DD;
    ld_f(feaG, 0, p);
    st_chunk(sT0, p);       // GEMM1's last reads were synced at loop end
    __syncthreads();
    ld_f(feaG, 1, p);

#pragma unroll 1
    for (int ch = 0; ch < 8; ch++) {
        float* cur = (ch & 1) ? sT1 : sT0;
        float* nxt = (ch & 1) ? sT0 : sT1;
        if (ch + 1 < 8) st_chunk(nxt, p);
        if (ch + 2 < 8) ld_f(feaG, ch + 2, p);
        compute(cur, sAssign + n0 * 128 + ch * CH, 128, acc2);
        __syncthreads();
    }

    // ---- write out: out[node][lane+32j] ----
#pragma unroll
    for (int i = 0; i < 8; i++) {
        float* orow = out + (size_t)(node0 + n0 + i) * 128;
#pragma unroll
        for (int j = 0; j < 4; j++) {
            float2 q = unpack2(acc2[i][j]);
            orow[lane + 32 * j] = q.x + q.y;
        }
    }
}

// ---------------- launch (4 kernels; profiler lands on k_fused = #4) -------
extern "C" void kernel_launch(void* const* d_in, const int* in_sizes, int n_in,
                              void* d_out, int out_size) {
    (void)in_sizes; (void)n_in; (void)out_size;
    const float* h    = (const float*)d_in[0];
    const float* fea  = (const float*)d_in[1];
    const float* Ws   = (const float*)d_in[2];
    const float* Wn   = (const float*)d_in[3];
    const float* bias = (const float*)d_in[4];
    const void*  esrc = d_in[5];
    const void*  edst = d_in[6];
    float* out = (float*)d_out;

    cudaFuncSetAttribute(k_fused, cudaFuncAttributeMaxDynamicSharedMemorySize,
                         SMEM_BYTES);

    k_count<<<(EDGES + 255) / 256, 256>>>(edst);
    k_scan <<<1, 1024>>>();
    k_fill <<<(EDGES + 255) / 256, 256>>>(esrc, edst);
    k_fused<<<NTOT / 64, 256, SMEM_BYTES>>>(h, fea, Ws, Wn, bias, out);
}